// round 12
// baseline (speedup 1.0000x reference)
#include <cuda_runtime.h>
#include <cuda_fp16.h>
#include <cstdint>

#define WINDOW   128
#define EDIM     64
#define SEQQ     4096
#define NWIN     32
#define THREADS  256
// scale * log2(e): S computed in log2 domain, exp = ex2.approx
#define SCALE_L2E 0.180336880f

// padded smem row stride (halves): 144B -> ldmatrix row ptrs conflict-free
#define RS 72

// smem (half units): K[256 rows] + X[256 rows].
// X holds Q (128 rows) during phase 1, then V (256 rows) for the mainloop.
#define O_K  0
#define O_X  (256 * RS)
#define SMEM_HALVES (512 * RS)
#define SMEM_BYTES  (SMEM_HALVES * 2 + 32)   // 73760

// fp32-accumulating HMMA (for O and l)
__device__ __forceinline__ void mma16816(float* c, const uint32_t* a, const uint32_t* b) {
    asm volatile(
        "mma.sync.aligned.m16n8k16.row.col.f32.f16.f16.f32 "
        "{%0,%1,%2,%3}, {%4,%5,%6,%7}, {%8,%9}, {%0,%1,%2,%3};"
        : "+f"(c[0]), "+f"(c[1]), "+f"(c[2]), "+f"(c[3])
        : "r"(a[0]), "r"(a[1]), "r"(a[2]), "r"(a[3]), "r"(b[0]), "r"(b[1]));
}
// fp16-accumulating HMMA (for S): C/D = 2 packed half2 regs
__device__ __forceinline__ void mma16816h(uint32_t* c, const uint32_t* a, const uint32_t* b) {
    asm volatile(
        "mma.sync.aligned.m16n8k16.row.col.f16.f16.f16.f16 "
        "{%0,%1}, {%2,%3,%4,%5}, {%6,%7}, {%0,%1};"
        : "+r"(c[0]), "+r"(c[1])
        : "r"(a[0]), "r"(a[1]), "r"(a[2]), "r"(a[3]), "r"(b[0]), "r"(b[1]));
}
__device__ __forceinline__ void ldm_x4(uint32_t* r, uint32_t addr) {
    asm volatile("ldmatrix.sync.aligned.m8n8.x4.shared.b16 {%0,%1,%2,%3}, [%4];"
        : "=r"(r[0]), "=r"(r[1]), "=r"(r[2]), "=r"(r[3]) : "r"(addr));
}
__device__ __forceinline__ void ldm_x4_t(uint32_t* r, uint32_t addr) {
    asm volatile("ldmatrix.sync.aligned.m8n8.x4.trans.shared.b16 {%0,%1,%2,%3}, [%4];"
        : "=r"(r[0]), "=r"(r[1]), "=r"(r[2]), "=r"(r[3]) : "r"(addr));
}
__device__ __forceinline__ void ldm_x2_t(uint32_t* r, uint32_t addr) {
    asm volatile("ldmatrix.sync.aligned.m8n8.x2.trans.shared.b16 {%0,%1}, [%2];"
        : "=r"(r[0]), "=r"(r[1]) : "r"(addr));
}
__device__ __forceinline__ uint32_t smem_u32(const void* p) {
    uint32_t a;
    asm("{ .reg .u64 t; cvta.to.shared.u64 t, %1; cvt.u32.u64 %0, t; }" : "=r"(a) : "l"(p));
    return a;
}
__device__ __forceinline__ uint32_t ex2_h2(uint32_t x) {
    uint32_t r;
    asm("ex2.approx.f16x2 %0, %1;" : "=r"(r) : "r"(x));
    return r;
}
__device__ __forceinline__ uint32_t mul_h2(uint32_t a, uint32_t b) {
    uint32_t r;
    asm("mul.rn.f16x2 %0, %1, %2;" : "=r"(r) : "r"(a), "r"(b));
    return r;
}

// One key-chunk, processed TILE-WISE (S-tile -> exp2 -> PV-tile) to keep the
// transient register set tiny (s2 = 4 regs). fp16 S accumulators; the S
// C-fragment IS the PV A-fragment (FA2 identity, zero repack).
template<int NT, bool DOMASK>
__device__ __forceinline__ void chunk_body(
    int jb, uint32_t sbK, uint32_t sbV,
    uint32_t koff, uint32_t voff, uint32_t voff2,
    const uint32_t (&qa)[4][4], float (&o)[8][4], float (&oL)[4],
    int lim0, int lim1)
{
    #pragma unroll
    for (int t = 0; t < NT; ++t) {
        const int j16 = jb + 16 * t;

        // ---- S tile: 16 keys, fp16 accum ----
        uint32_t s2[4] = {0u, 0u, 0u, 0u};   // [0,1]: keys +0..7; [2,3]: +8..15
        const uint32_t kcb = sbK + 2u * j16 * RS + koff;
        #pragma unroll
        for (int ks = 0; ks < 4; ++ks) {
            uint32_t b[4];
            ldm_x4(b, kcb + 2u * 16 * ks);
            mma16816h(s2,     qa[ks], b);
            mma16816h(s2 + 2, qa[ks], b + 2);
        }

        // ---- exp2 (+ 0/1 half2 mask) ----
        #pragma unroll
        for (int sub = 0; sub < 2; ++sub) {
            uint32_t p0 = ex2_h2(s2[2 * sub]);
            uint32_t p1 = ex2_h2(s2[2 * sub + 1]);
            if (DOMASK) {
                const int col0 = j16 + 8 * sub;   // caller folded 2*tig into lims
                uint32_t m0 = (col0 <= lim0 ? 0x3C00u : 0u) | (col0 + 1 <= lim0 ? 0x3C000000u : 0u);
                uint32_t m1 = (col0 <= lim1 ? 0x3C00u : 0u) | (col0 + 1 <= lim1 ? 0x3C000000u : 0u);
                p0 = mul_h2(p0, m0);
                p1 = mul_h2(p1, m1);
            }
            s2[2 * sub]     = p0;
            s2[2 * sub + 1] = p1;
        }
        // A-fragment = {rowsg/k0-7, rowsg8/k0-7, rowsg/k8-15, rowsg8/k8-15} = s2 as-is

        // ---- PV tile: O += P x V (+ l ones-tile) ----
        const uint32_t vcb = sbV + 2u * j16 * RS;
        #pragma unroll
        for (int ep = 0; ep < 4; ++ep) {
            uint32_t b[4];
            ldm_x4_t(b, vcb + voff + 2u * 16 * ep);
            mma16816(o[2 * ep],     s2, b);
            mma16816(o[2 * ep + 1], s2, b + 2);
        }
        uint32_t bl[2];
        ldm_x2_t(bl, vcb + voff2);
        mma16816(oL, s2, bl);
    }
}

__global__ __launch_bounds__(THREADS, 3)
void lattn_hmma(const float* __restrict__ q, const float* __restrict__ k,
                const float* __restrict__ v, float* __restrict__ out)
{
    extern __shared__ __half smem[];
    const uint32_t sb  = smem_u32(smem);
    const uint32_t sbK = sb + O_K * 2;
    const uint32_t sbX = sb + O_X * 2;   // Q in phase 1, V in mainloop

    const int tid = threadIdx.x;
    const int w   = tid >> 5;
    const int ln  = tid & 31;
    const int g   = ln >> 2;
    const int tig = ln & 3;
    // balanced SMSP map: warps {s, s+4} host wl {s, 7-s}
    const int wl  = (w < 4) ? w : 11 - w;
    const int win = blockIdx.x;
    const int bh  = blockIdx.y;
    const bool have_back = (win > 0);

    const long long qrow0 = (long long)bh * SEQQ + (long long)win * WINDOW;
    const long long krow0 = qrow0 - WINDOW;

    const float4* qg4 = (const float4*)(q + qrow0 * EDIM);
    const float4* kg4 = (const float4*)(k + krow0 * EDIM);
    const float4* vg4 = (const float4*)(v + krow0 * EDIM);

    // ---- phase 1: Q (scaled) -> X, K -> K region ----
    #pragma unroll
    for (int it = 0; it < 8; ++it) {
        int idx = it * THREADS + tid;          // 0..2047
        int row = idx >> 4, c4 = idx & 15;
        float4 f = qg4[idx];
        __half2 a = __floats2half2_rn(f.x * SCALE_L2E, f.y * SCALE_L2E);
        __half2 b = __floats2half2_rn(f.z * SCALE_L2E, f.w * SCALE_L2E);
        *(uint2*)&smem[O_X + row * RS + 4 * c4] =
            make_uint2(*(uint32_t*)&a, *(uint32_t*)&b);
    }
    #pragma unroll
    for (int it = 0; it < 16; ++it) {
        int idx = it * THREADS + tid;          // 0..4095
        int row = idx >> 4, c4 = idx & 15;
        if (have_back || row >= WINDOW) {
            float4 f = kg4[idx];
            __half2 a = __floats2half2_rn(f.x, f.y);
            __half2 b = __floats2half2_rn(f.z, f.w);
            *(uint2*)&smem[O_K + row * RS + 4 * c4] =
                make_uint2(*(uint32_t*)&a, *(uint32_t*)&b);
        }
    }
    __syncthreads();

    // per-lane ldmatrix base offsets (bytes)
    const uint32_t koff  = 2u * (((ln & 7) + ((ln & 16) >> 1)) * RS + (ln & 8));
    const uint32_t voff  = 2u * (((ln & 7) + (ln & 8)) * RS + ((ln & 16) >> 1));
    const uint32_t voff2 = 2u * (((ln & 7) + (ln & 8)) * RS + 64);

    // ---- resident Q A-fragments (from X before V overwrites it) ----
    uint32_t qa[4][4];
    {
        const uint32_t qbase = sbX + 2u * (16 * wl) * RS + voff;
        #pragma unroll
        for (int ks = 0; ks < 4; ++ks)
            ldm_x4(qa[ks], qbase + 2u * 16 * ks);
    }
    __syncthreads();

    // ---- phase 2: V -> X (+ ones column at e=64) ----
    #pragma unroll
    for (int it = 0; it < 16; ++it) {
        int idx = it * THREADS + tid;          // 0..4095
        int row = idx >> 4, c4 = idx & 15;
        if (have_back || row >= WINDOW) {
            float4 f = vg4[idx];
            __half2 a = __floats2half2_rn(f.x, f.y);
            __half2 b = __floats2half2_rn(f.z, f.w);
            *(uint2*)&smem[O_X + row * RS + 4 * c4] =
                make_uint2(*(uint32_t*)&a, *(uint32_t*)&b);
        }
    }
    {
        const __half2 one0 = __floats2half2_rn(1.f, 0.f);
        const __half2 zz   = __floats2half2_rn(0.f, 0.f);
        #pragma unroll
        for (int it = 0; it < 4; ++it) {
            int idx = it * THREADS + tid;      // 0..1023
            int row = idx >> 2, cc = idx & 3;
            *(__half2*)&smem[O_X + row * RS + 64 + 2 * cc] = (cc == 0) ? one0 : zz;
        }
    }
    __syncthreads();

    const int row0 = 16 * wl + g;
    const int row1 = row0 + 8;

    float o[8][4];
    #pragma unroll
    for (int nt = 0; nt < 8; ++nt)
        #pragma unroll
        for (int i = 0; i < 4; ++i) o[nt][i] = 0.f;
    float oL[4] = {0.f, 0.f, 0.f, 0.f};

    // lims pre-shifted by -2*tig so chunk body compares against jb+8sub(+1)
    const int lim0 = row0 + WINDOW - 2 * tig;
    const int lim1 = row1 + WINDOW - 2 * tig;

    // chunks 0,1: unmasked, all 4 tiles (skip for window 0)
    if (have_back) {
        chunk_body<4, false>(0,  sbK, sbX, koff, voff, voff2, qa, o, oL, lim0, lim1);
        chunk_body<4, false>(64, sbK, sbX, koff, voff, voff2, qa, o, oL, lim0, lim1);
    }
    // chunk 2 (keys 128..191): rows 0..31 only ever see keys <=159 -> 2 tiles
    if (wl < 2)
        chunk_body<2, true>(128, sbK, sbX, koff, voff, voff2, qa, o, oL, lim0, lim1);
    else
        chunk_body<4, true>(128, sbK, sbX, koff, voff, voff2, qa, o, oL, lim0, lim1);
    // chunk 3 (keys 192..255): rows <64 see none; rows 64..95 see <=223 -> 2 tiles
    if (wl >= 4) {
        if (wl < 6)
            chunk_body<2, true>(192, sbK, sbX, koff, voff, voff2, qa, o, oL, lim0, lim1);
        else
            chunk_body<4, true>(192, sbK, sbX, koff, voff, voff2, qa, o, oL, lim0, lim1);
    }

    // ---- l from ones column (tig==0 lanes), normalize, store ----
    const float l0 = __shfl_sync(0xFFFFFFFFu, oL[0], ln & 28);
    const float l1 = __shfl_sync(0xFFFFFFFFu, oL[2], ln & 28);
    const float r0 = 1.f / l0;
    const float r1 = 1.f / l1;

    float* ob = out + qrow0 * EDIM;
    #pragma unroll
    for (int nt = 0; nt < 8; ++nt) {
        int e0 = 8 * nt + 2 * tig;
        float2 v0 = make_float2(o[nt][0] * r0, o[nt][1] * r0);
        float2 v1 = make_float2(o[nt][2] * r1, o[nt][3] * r1);
        *(float2*)&ob[(long long)row0 * EDIM + e0] = v0;
        *(float2*)&ob[(long long)row1 * EDIM + e0] = v1;
    }
}

extern "C" void kernel_launch(void* const* d_in, const int* in_sizes, int n_in,
                              void* d_out, int out_size)
{
    const float* q = (const float*)d_in[0];
    const float* k = (const float*)d_in[1];
    const float* v = (const float*)d_in[2];
    float* out = (float*)d_out;

    const int bh_count = in_sizes[0] / (SEQQ * EDIM);   // b*h = 32

    cudaFuncSetAttribute(lattn_hmma, cudaFuncAttributeMaxDynamicSharedMemorySize, SMEM_BYTES);

    dim3 grid(NWIN, bh_count);
    lattn_hmma<<<grid, THREADS, SMEM_BYTES>>>(q, k, v, out);
}

// round 13
// speedup vs baseline: 1.0033x; 1.0033x over previous
#include <cuda_runtime.h>
#include <cuda_fp16.h>
#include <cstdint>

#define WINDOW   128
#define EDIM     64
#define SEQQ     4096
#define NWIN     32
#define THREADS  256
// scale * log2(e): S computed in log2 domain, exp = ex2.approx
#define SCALE_L2E 0.180336880f

// padded smem row stride (halves): 144B -> ldmatrix row ptrs conflict-free
#define RS 72

// smem (half units): K[256 rows] + X[256 rows].
// X holds Q (128 rows) during phase 1, then V (256 rows) for the mainloop.
#define O_K  0
#define O_X  (256 * RS)
#define SMEM_HALVES (512 * RS)
#define SMEM_BYTES  (SMEM_HALVES * 2 + 32)   // 73760 -> 3 CTAs/SM

// fp32-accumulating HMMA (for O and l)
__device__ __forceinline__ void mma16816(float* c, const uint32_t* a, const uint32_t* b) {
    asm volatile(
        "mma.sync.aligned.m16n8k16.row.col.f32.f16.f16.f32 "
        "{%0,%1,%2,%3}, {%4,%5,%6,%7}, {%8,%9}, {%0,%1,%2,%3};"
        : "+f"(c[0]), "+f"(c[1]), "+f"(c[2]), "+f"(c[3])
        : "r"(a[0]), "r"(a[1]), "r"(a[2]), "r"(a[3]), "r"(b[0]), "r"(b[1]));
}
// fp16-accumulating HMMA (for S): C/D = 2 packed half2 regs
__device__ __forceinline__ void mma16816h(uint32_t* c, const uint32_t* a, const uint32_t* b) {
    asm volatile(
        "mma.sync.aligned.m16n8k16.row.col.f16.f16.f16.f16 "
        "{%0,%1}, {%2,%3,%4,%5}, {%6,%7}, {%0,%1};"
        : "+r"(c[0]), "+r"(c[1])
        : "r"(a[0]), "r"(a[1]), "r"(a[2]), "r"(a[3]), "r"(b[0]), "r"(b[1]));
}
__device__ __forceinline__ void ldm_x4(uint32_t* r, uint32_t addr) {
    asm volatile("ldmatrix.sync.aligned.m8n8.x4.shared.b16 {%0,%1,%2,%3}, [%4];"
        : "=r"(r[0]), "=r"(r[1]), "=r"(r[2]), "=r"(r[3]) : "r"(addr));
}
__device__ __forceinline__ void ldm_x4_t(uint32_t* r, uint32_t addr) {
    asm volatile("ldmatrix.sync.aligned.m8n8.x4.trans.shared.b16 {%0,%1,%2,%3}, [%4];"
        : "=r"(r[0]), "=r"(r[1]), "=r"(r[2]), "=r"(r[3]) : "r"(addr));
}
__device__ __forceinline__ void ldm_x2_t(uint32_t* r, uint32_t addr) {
    asm volatile("ldmatrix.sync.aligned.m8n8.x2.trans.shared.b16 {%0,%1}, [%2];"
        : "=r"(r[0]), "=r"(r[1]) : "r"(addr));
}
__device__ __forceinline__ uint32_t smem_u32(const void* p) {
    uint32_t a;
    asm("{ .reg .u64 t; cvta.to.shared.u64 t, %1; cvt.u32.u64 %0, t; }" : "=r"(a) : "l"(p));
    return a;
}
__device__ __forceinline__ uint32_t ex2_h2(uint32_t x) {
    uint32_t r;
    asm("ex2.approx.f16x2 %0, %1;" : "=r"(r) : "r"(x));
    return r;
}
__device__ __forceinline__ uint32_t mul_h2(uint32_t a, uint32_t b) {
    uint32_t r;
    asm("mul.rn.f16x2 %0, %1, %2;" : "=r"(r) : "r"(a), "r"(b));
    return r;
}

// One key-chunk, STAGE-WISE (all S MMAs -> all exp2 -> all PV MMAs) for max
// ILP (R11-proven). fp16 S accumulators; the S C-fragment IS the PV
// A-fragment (FA2 identity, zero repack).
template<int NT, bool DOMASK>
__device__ __forceinline__ void chunk_body(
    int jb, uint32_t sbK, uint32_t sbV,
    uint32_t koff, uint32_t voff, uint32_t voff2,
    const uint32_t (&qa)[4][4], float (&o)[8][4], float (&oL)[4],
    int lim0, int lim1)
{
    // s2[nt][0]: rows g, cols (jb+8nt+2tig,+1); s2[nt][1]: rows g+8
    uint32_t s2[2 * NT][2];
    #pragma unroll
    for (int nt = 0; nt < 2 * NT; ++nt) { s2[nt][0] = 0u; s2[nt][1] = 0u; }

    const uint32_t kcb = sbK + 2u * jb * RS + koff;
    #pragma unroll
    for (int ks = 0; ks < 4; ++ks) {
        #pragma unroll
        for (int ntp = 0; ntp < NT; ++ntp) {
            uint32_t b[4];
            ldm_x4(b, kcb + 2u * (16 * ntp * RS + 16 * ks));
            mma16816h(s2[2 * ntp],     qa[ks], b);
            mma16816h(s2[2 * ntp + 1], qa[ks], b + 2);
        }
    }

    // exp2 in fp16, then zero masked lanes via 0/1 half2 multiply
    #pragma unroll
    for (int nt = 0; nt < 2 * NT; ++nt) {
        uint32_t p0 = ex2_h2(s2[nt][0]);
        uint32_t p1 = ex2_h2(s2[nt][1]);
        if (DOMASK) {
            const int col0 = jb + 8 * nt;          // caller folded 2*tig into lims
            uint32_t m0 = (col0 <= lim0 ? 0x3C00u : 0u) | (col0 + 1 <= lim0 ? 0x3C000000u : 0u);
            uint32_t m1 = (col0 <= lim1 ? 0x3C00u : 0u) | (col0 + 1 <= lim1 ? 0x3C000000u : 0u);
            p0 = mul_h2(p0, m0);
            p1 = mul_h2(p1, m1);
        }
        s2[nt][0] = p0;
        s2[nt][1] = p1;
    }

    const uint32_t vcb = sbV + 2u * jb * RS;
    #pragma unroll
    for (int t = 0; t < NT; ++t) {
        // A-fragment for keys 16t..16t+15 (FA2 layout identity)
        uint32_t pa[4] = { s2[2 * t][0], s2[2 * t][1], s2[2 * t + 1][0], s2[2 * t + 1][1] };
        #pragma unroll
        for (int ep = 0; ep < 4; ++ep) {
            uint32_t b[4];
            ldm_x4_t(b, vcb + voff + 2u * (16 * t * RS + 16 * ep));
            mma16816(o[2 * ep],     pa, b);
            mma16816(o[2 * ep + 1], pa, b + 2);
        }
        uint32_t bl[2];
        ldm_x2_t(bl, vcb + voff2 + 2u * (16 * t * RS));
        mma16816(oL, pa, bl);
    }
}

__global__ __launch_bounds__(THREADS, 3)
void lattn_hmma(const float* __restrict__ q, const float* __restrict__ k,
                const float* __restrict__ v, float* __restrict__ out)
{
    extern __shared__ __half smem[];
    const uint32_t sb  = smem_u32(smem);
    const uint32_t sbK = sb + O_K * 2;
    const uint32_t sbX = sb + O_X * 2;   // Q in phase 1, V in mainloop

    const int tid = threadIdx.x;
    const int w   = tid >> 5;
    const int ln  = tid & 31;
    const int g   = ln >> 2;
    const int tig = ln & 3;
    // balanced SMSP map: warps {s, s+4} host wl {s, 7-s}
    const int wl  = (w < 4) ? w : 11 - w;
    const int win = blockIdx.x;
    const int bh  = blockIdx.y;
    const bool have_back = (win > 0);

    const long long qrow0 = (long long)bh * SEQQ + (long long)win * WINDOW;
    const long long krow0 = qrow0 - WINDOW;

    const float4* qg4 = (const float4*)(q + qrow0 * EDIM);
    const float4* kg4 = (const float4*)(k + krow0 * EDIM);
    const float4* vg4 = (const float4*)(v + krow0 * EDIM);

    // ---- phase 1: Q (scaled) -> X, K -> K region ----
    #pragma unroll
    for (int it = 0; it < 8; ++it) {
        int idx = it * THREADS + tid;          // 0..2047
        int row = idx >> 4, c4 = idx & 15;
        float4 f = qg4[idx];
        __half2 a = __floats2half2_rn(f.x * SCALE_L2E, f.y * SCALE_L2E);
        __half2 b = __floats2half2_rn(f.z * SCALE_L2E, f.w * SCALE_L2E);
        *(uint2*)&smem[O_X + row * RS + 4 * c4] =
            make_uint2(*(uint32_t*)&a, *(uint32_t*)&b);
    }
    #pragma unroll
    for (int it = 0; it < 16; ++it) {
        int idx = it * THREADS + tid;          // 0..4095
        int row = idx >> 4, c4 = idx & 15;
        if (have_back || row >= WINDOW) {
            float4 f = kg4[idx];
            __half2 a = __floats2half2_rn(f.x, f.y);
            __half2 b = __floats2half2_rn(f.z, f.w);
            *(uint2*)&smem[O_K + row * RS + 4 * c4] =
                make_uint2(*(uint32_t*)&a, *(uint32_t*)&b);
        }
    }
    __syncthreads();

    // per-lane ldmatrix base offsets (bytes)
    const uint32_t koff  = 2u * (((ln & 7) + ((ln & 16) >> 1)) * RS + (ln & 8));
    const uint32_t voff  = 2u * (((ln & 7) + (ln & 8)) * RS + ((ln & 16) >> 1));
    const uint32_t voff2 = 2u * (((ln & 7) + (ln & 8)) * RS + 64);

    // ---- resident Q A-fragments (from X before V overwrites it) ----
    uint32_t qa[4][4];
    {
        const uint32_t qbase = sbX + 2u * (16 * wl) * RS + voff;
        #pragma unroll
        for (int ks = 0; ks < 4; ++ks)
            ldm_x4(qa[ks], qbase + 2u * 16 * ks);
    }
    __syncthreads();

    // ---- phase 2: V -> X (+ ones column at e=64) ----
    #pragma unroll
    for (int it = 0; it < 16; ++it) {
        int idx = it * THREADS + tid;          // 0..4095
        int row = idx >> 4, c4 = idx & 15;
        if (have_back || row >= WINDOW) {
            float4 f = vg4[idx];
            __half2 a = __floats2half2_rn(f.x, f.y);
            __half2 b = __floats2half2_rn(f.z, f.w);
            *(uint2*)&smem[O_X + row * RS + 4 * c4] =
                make_uint2(*(uint32_t*)&a, *(uint32_t*)&b);
        }
    }
    {
        const __half2 one0 = __floats2half2_rn(1.f, 0.f);
        const __half2 zz   = __floats2half2_rn(0.f, 0.f);
        #pragma unroll
        for (int it = 0; it < 4; ++it) {
            int idx = it * THREADS + tid;      // 0..1023
            int row = idx >> 2, cc = idx & 3;
            *(__half2*)&smem[O_X + row * RS + 64 + 2 * cc] = (cc == 0) ? one0 : zz;
        }
    }
    __syncthreads();

    const int row0 = 16 * wl + g;
    const int row1 = row0 + 8;

    float o[8][4];
    #pragma unroll
    for (int nt = 0; nt < 8; ++nt)
        #pragma unroll
        for (int i = 0; i < 4; ++i) o[nt][i] = 0.f;
    float oL[4] = {0.f, 0.f, 0.f, 0.f};

    // lims pre-shifted by -2*tig so chunk body compares against jb+8nt(+1)
    const int lim0 = row0 + WINDOW - 2 * tig;
    const int lim1 = row1 + WINDOW - 2 * tig;

    // chunks 0,1: unmasked, all 4 tiles (skip for window 0)
    if (have_back) {
        chunk_body<4, false>(0,  sbK, sbX, koff, voff, voff2, qa, o, oL, lim0, lim1);
        chunk_body<4, false>(64, sbK, sbX, koff, voff, voff2, qa, o, oL, lim0, lim1);
    }
    // chunk 2 (keys 128..191): rows 0..31 only ever see keys <=159 -> 2 tiles
    if (wl < 2)
        chunk_body<2, true>(128, sbK, sbX, koff, voff, voff2, qa, o, oL, lim0, lim1);
    else
        chunk_body<4, true>(128, sbK, sbX, koff, voff, voff2, qa, o, oL, lim0, lim1);
    // chunk 3 (keys 192..255): rows <64 see none; rows 64..95 see <=223 -> 2 tiles
    if (wl >= 4) {
        if (wl < 6)
            chunk_body<2, true>(192, sbK, sbX, koff, voff, voff2, qa, o, oL, lim0, lim1);
        else
            chunk_body<4, true>(192, sbK, sbX, koff, voff, voff2, qa, o, oL, lim0, lim1);
    }

    // ---- l from ones column (tig==0 lanes), normalize, store ----
    const float l0 = __shfl_sync(0xFFFFFFFFu, oL[0], ln & 28);
    const float l1 = __shfl_sync(0xFFFFFFFFu, oL[2], ln & 28);
    const float r0 = 1.f / l0;
    const float r1 = 1.f / l1;

    float* ob = out + qrow0 * EDIM;
    #pragma unroll
    for (int nt = 0; nt < 8; ++nt) {
        int e0 = 8 * nt + 2 * tig;
        float2 v0 = make_float2(o[nt][0] * r0, o[nt][1] * r0);
        float2 v1 = make_float2(o[nt][2] * r1, o[nt][3] * r1);
        *(float2*)&ob[(long long)row0 * EDIM + e0] = v0;
        *(float2*)&ob[(long long)row1 * EDIM + e0] = v1;
    }
}

extern "C" void kernel_launch(void* const* d_in, const int* in_sizes, int n_in,
                              void* d_out, int out_size)
{
    const float* q = (const float*)d_in[0];
    const float* k = (const float*)d_in[1];
    const float* v = (const float*)d_in[2];
    float* out = (float*)d_out;

    const int bh_count = in_sizes[0] / (SEQQ * EDIM);   // b*h = 32

    cudaFuncSetAttribute(lattn_hmma, cudaFuncAttributeMaxDynamicSharedMemorySize, SMEM_BYTES);

    dim3 grid(NWIN, bh_count);
    lattn_hmma<<<grid, THREADS, SMEM_BYTES>>>(q, k, v, out);
}